// round 15
// baseline (speedup 1.0000x reference)
#include <cuda_runtime.h>
#include <cuda_bf16.h>
#include <cuda_fp16.h>
#include <math.h>
#include <stdint.h>

#define NN 50000

// ---------------- scratch (device globals; no allocations allowed) ----------
// Split per-node features. A = dst-side, B = src-side. Stride 6*O bytes:
//   [0    ,4O ) qk interleaved: group g (4 ch): [16g,16g+8)=q[4g..4g+3] bf16,
//                                               [16g+8,16g+16)=k[4g..4g+3] bf16
//   [4O   ,6O ) v  fp16[O]
__device__ __align__(16) unsigned char g_featA[NN * 768];
__device__ __align__(16) unsigned char g_featB[NN * 768];
__device__ float g_x0[NN * 128];      // relu(layer0 out), tf32-rounded
__device__ float g_h1[NN * 64];       // relu(layer1 out), tf32-rounded
__device__ float g_acc[NN * 128];     // edge-aggregation accumulator (f32)
__device__ float g_cnt[NN];           // edge count per dst
__device__ float g_wcatT[768 * 128];  // transposed transformed weights [M][K], tf32
__device__ float g_bcat[768];         // concatenated bias (bias only on A columns)

__device__ __forceinline__ float rna_tf32(float v) {
    float o;
    asm("cvt.rna.tf32.f32 %0, %1;" : "=f"(o) : "f"(v));
    return o;
}
__device__ __forceinline__ float ex2f(float v) {
    float o;
    asm("ex2.approx.f32 %0, %1;" : "=f"(o) : "f"(v));
    return o;
}
__device__ __forceinline__ float rcpf(float v) {
    float o;
    asm("rcp.approx.f32 %0, %1;" : "=f"(o) : "f"(v));
    return o;
}

// ---------------- build W_catT[col][c] = rna([Wtop-Wbot | Wbot]); zero cnt ---
__global__ void build_wcat(const float* __restrict__ wq, const float* __restrict__ wk,
                           const float* __restrict__ wv, const float* __restrict__ bq,
                           const float* __restrict__ bk, const float* __restrict__ bv,
                           int C, int O) {
    int M = 6 * O;
    int idx = blockIdx.x * blockDim.x + threadIdx.x;
    if (idx < C * M) {
        int c = idx / M, col = idx % M;
        int grp = col / O, j = col % O;
        const float* w = (grp < 2) ? wq : (grp < 4 ? wk : wv);
        float top = w[c * O + j];
        float bot = w[(C + c) * O + j];
        float val = (grp & 1) ? bot : (top - bot);
        g_wcatT[(size_t)col * C + c] = rna_tf32(val);
    }
    if (idx < M) {
        int grp = idx / O, j = idx % O;
        const float* b = (grp < 2) ? bq : (grp < 4 ? bk : bv);
        g_bcat[idx] = (grp & 1) ? 0.0f : b[j];
    }
    if (idx < NN) g_cnt[idx] = 0.0f;  // prepare edge-count for this layer
}

// ---------------- one-time acc zero (vectorized) -----------------------------
__global__ void zero_acc(int n4) {
    int idx = blockIdx.x * blockDim.x + threadIdx.x;
    if (idx < n4) ((float4*)g_acc)[idx] = make_float4(0.f, 0.f, 0.f, 0.f);
}

// ---------------- tf32 tensor-core GEMM --------------------------------------
// feat = A(NxK) @ g_wcatT^T + bias, written to split A/B node layout
// (qk interleaved bf16, v fp16). srcsel: 0 -> Aext, 1 -> g_x0, 2 -> g_h1.
// ROUND: in-register rna of A fragments (only needed for external x).
template <int K, int O, bool ROUND>
__global__ __launch_bounds__(256, 2) void mma_gemm(const float* __restrict__ Aext,
                                                   int srcsel, int N) {
    const float* A = (srcsel == 0) ? Aext : ((srcsel == 1) ? g_x0 : g_h1);
    constexpr int PAD = 20;
    __shared__ float As[2][128 * PAD];
    __shared__ float Bs[2][128 * PAD];

    const int tid = threadIdx.x;
    const int lane = tid & 31;
    const int wid = tid >> 5;
    const int wm = (wid & 1) * 64;
    const int wn = (wid >> 1) * 32;
    const int bm = blockIdx.y * 128;
    const int bn = blockIdx.x * 128;

    float acc[4][4][4];
#pragma unroll
    for (int a = 0; a < 4; a++)
#pragma unroll
        for (int b = 0; b < 4; b++)
#pragma unroll
            for (int c = 0; c < 4; c++) acc[a][b][c] = 0.0f;

    const int r_ld = tid >> 1;
    const int ch0 = (tid & 1) * 2;
    const int garow = bm + r_ld;
    const float* aptr = A + (size_t)(garow < N ? garow : 0) * K;
    const int asz = (garow < N) ? 16 : 0;
    const float* bptr = g_wcatT + (size_t)(bn + r_ld) * K;

#define SMADDR(p) ((uint32_t)__cvta_generic_to_shared(p))

#define LOAD_STAGE(buf, k0)                                                          \
    {                                                                                \
        _Pragma("unroll") for (int i = 0; i < 2; i++) {                              \
            int ch = ch0 + i;                                                        \
            asm volatile("cp.async.cg.shared.global [%0], [%1], 16, %2;" ::"r"(      \
                             SMADDR(&As[buf][r_ld * PAD + ch * 4])),                 \
                         "l"(aptr + (k0) + ch * 4), "r"(asz));                       \
            asm volatile("cp.async.cg.shared.global [%0], [%1], 16;" ::"r"(          \
                             SMADDR(&Bs[buf][r_ld * PAD + ch * 4])),                 \
                         "l"(bptr + (k0) + ch * 4));                                 \
        }                                                                            \
        asm volatile("cp.async.commit_group;");                                      \
    }

    LOAD_STAGE(0, 0);
    constexpr int NIT = K / 16;
#pragma unroll
    for (int it = 0; it < NIT; it++) {
        const int buf = it & 1;
        if (it + 1 < NIT) {
            LOAD_STAGE(buf ^ 1, (it + 1) * 16);
            asm volatile("cp.async.wait_group 1;");
        } else {
            asm volatile("cp.async.wait_group 0;");
        }
        __syncthreads();

#pragma unroll
        for (int ks = 0; ks < 16; ks += 8) {
            uint32_t af[4][4];
#pragma unroll
            for (int mt = 0; mt < 4; mt++) {
                const float* p = &As[buf][(wm + mt * 16 + (lane & 15)) * PAD + ks +
                                          (lane >> 4) * 4];
                asm volatile(
                    "ldmatrix.sync.aligned.m8n8.x4.shared.b16 {%0,%1,%2,%3}, [%4];"
                    : "=r"(af[mt][0]), "=r"(af[mt][1]), "=r"(af[mt][2]), "=r"(af[mt][3])
                    : "r"(SMADDR(p)));
                if constexpr (ROUND) {
#pragma unroll
                    for (int r = 0; r < 4; r++)
                        af[mt][r] =
                            __float_as_uint(rna_tf32(__uint_as_float(af[mt][r])));
                }
            }
            uint32_t bf[2][4];
#pragma unroll
            for (int bi = 0; bi < 2; bi++) {
                const float* p = &Bs[buf][(wn + bi * 16 + (lane & 7) +
                                           ((lane >> 4) << 3)) *
                                              PAD +
                                          ks + ((lane >> 3) & 1) * 4];
                asm volatile(
                    "ldmatrix.sync.aligned.m8n8.x4.shared.b16 {%0,%1,%2,%3}, [%4];"
                    : "=r"(bf[bi][0]), "=r"(bf[bi][1]), "=r"(bf[bi][2]), "=r"(bf[bi][3])
                    : "r"(SMADDR(p)));
            }
#pragma unroll
            for (int mt = 0; mt < 4; mt++)
#pragma unroll
                for (int nt = 0; nt < 4; nt++) {
                    uint32_t b0 = bf[nt >> 1][(nt & 1) * 2];
                    uint32_t b1 = bf[nt >> 1][(nt & 1) * 2 + 1];
                    asm volatile(
                        "mma.sync.aligned.m16n8k8.row.col.f32.tf32.tf32.f32 "
                        "{%0,%1,%2,%3}, {%4,%5,%6,%7}, {%8,%9}, {%0,%1,%2,%3};"
                        : "+f"(acc[mt][nt][0]), "+f"(acc[mt][nt][1]),
                          "+f"(acc[mt][nt][2]), "+f"(acc[mt][nt][3])
                        : "r"(af[mt][0]), "r"(af[mt][1]), "r"(af[mt][2]),
                          "r"(af[mt][3]), "r"(b0), "r"(b1));
                }
        }
        __syncthreads();
    }

    // Epilogue: add bias, write split A/B layout (qk interleaved bf16, v fp16).
    // q pair at (j>>2)*16 + (j&3)*2 ; k pair same + 8 ; v pair at 4*O + j*2.
#pragma unroll
    for (int mt = 0; mt < 4; mt++) {
        int r = bm + wm + mt * 16 + (lane >> 2);
#pragma unroll
        for (int half = 0; half < 2; half++) {
            int rr = r + half * 8;
            if (rr < N) {
                unsigned char* baseA = g_featA + (size_t)rr * (6 * O);
                unsigned char* baseB = g_featB + (size_t)rr * (6 * O);
#pragma unroll
                for (int nt = 0; nt < 4; nt++) {
                    int c = bn + wn + nt * 8 + (lane & 3) * 2;
                    int grp = c / O;
                    int j = c - grp * O;
                    float ox = acc[mt][nt][half * 2 + 0] + g_bcat[c];
                    float oy = acc[mt][nt][half * 2 + 1] + g_bcat[c + 1];
                    unsigned char* base = (grp & 1) ? baseB : baseA;
                    int reg = grp >> 1;  // 0=q, 1=k, 2=v
                    if (reg < 2) {
                        __nv_bfloat162 h2 = __floats2bfloat162_rn(ox, oy);
                        *(__nv_bfloat162*)(base + (j >> 2) * 16 + (j & 3) * 2 +
                                           reg * 8) = h2;
                    } else {
                        __half2 h2 = __floats2half2_rn(ox, oy);
                        *(__half2*)(base + 4 * O + j * 2) = h2;
                    }
                }
            }
        }
    }
#undef LOAD_STAGE
#undef SMADDR
}

// ---------------- edge kernel, O=128: ONE edge per warp ----------------------
// CPT=4 channels/lane. One 16B qk load + one 8B v load per side (4 gathers).
__global__ __launch_bounds__(256) void edge_kernel128(const int* __restrict__ esrc,
                                                      const int* __restrict__ edst,
                                                      int E) {
    constexpr int O = 128;
    const float CEXP = 0.25f * 1.44269504f;

    int gwarp = (blockIdx.x * blockDim.x + threadIdx.x) >> 5;
    int lane = threadIdx.x & 31;
    if (gwarp >= E) return;

    int s = esrc[gwarp];
    int d = edst[gwarp];
    int dd = abs(d - s);
    float ew = (dd > 8) ? 1.0f : ((dd == 8) ? 0.0f : -1.0f);

    const unsigned char* fa = g_featA + (size_t)d * (6 * O);
    const unsigned char* fb = g_featB + (size_t)s * (6 * O);

    uint4 ua = __ldg((const uint4*)(fa + lane * 16));
    uint4 ub = __ldg((const uint4*)(fb + lane * 16));
    uint2 uva = __ldg((const uint2*)(fa + 4 * O + lane * 8));
    uint2 uvb = __ldg((const uint2*)(fb + 4 * O + lane * 8));

    __nv_bfloat162 qa2[2] = {*(__nv_bfloat162*)&ua.x, *(__nv_bfloat162*)&ua.y};
    __nv_bfloat162 ka2[2] = {*(__nv_bfloat162*)&ua.z, *(__nv_bfloat162*)&ua.w};
    __nv_bfloat162 qb2[2] = {*(__nv_bfloat162*)&ub.x, *(__nv_bfloat162*)&ub.y};
    __nv_bfloat162 kb2[2] = {*(__nv_bfloat162*)&ub.z, *(__nv_bfloat162*)&ub.w};
    __half2 va2[2] = {*(__half2*)&uva.x, *(__half2*)&uva.y};
    __half2 vb2[2] = {*(__half2*)&uvb.x, *(__half2*)&uvb.y};

    float p[4], vsum[4], sum = 0.0f;
#pragma unroll
    for (int h = 0; h < 2; h++) {
        __nv_bfloat162 t = __hmul2(__hadd2(qa2[h], qb2[h]), __hadd2(ka2[h], kb2[h]));
        float2 f = __bfloat1622float2(t);
        p[2 * h] = ex2f(f.x * CEXP);
        p[2 * h + 1] = ex2f(f.y * CEXP);
        sum += p[2 * h] + p[2 * h + 1];
        float2 fa2 = __half22float2(va2[h]);
        float2 fb2 = __half22float2(vb2[h]);
        vsum[2 * h] = fa2.x + fb2.x;
        vsum[2 * h + 1] = fa2.y + fb2.y;
    }
    sum += __shfl_xor_sync(0xFFFFFFFFu, sum, 1);
    sum += __shfl_xor_sync(0xFFFFFFFFu, sum, 2);
    float w = ew * rcpf(sum);

    float ctx[4];
#pragma unroll
    for (int i = 0; i < 4; i++) ctx[i] = p[i] * w * vsum[i];

    float* ap = g_acc + (size_t)d * O + lane * 4;
    asm volatile("red.global.add.v4.f32 [%0], {%1, %2, %3, %4};" ::"l"(ap),
                 "f"(ctx[0]), "f"(ctx[1]), "f"(ctx[2]), "f"(ctx[3])
                 : "memory");
    if (lane == 0) atomicAdd(&g_cnt[d], 1.0f);
}

// ---------------- edge kernel, O=64: TWO edges per warp ----------------------
// 16 lanes/edge, CPT=4, head = 2 lanes. Same 4-gather pattern.
__global__ __launch_bounds__(256) void edge_kernel64(const int* __restrict__ esrc,
                                                     const int* __restrict__ edst,
                                                     int E) {
    constexpr int O = 64;
    const float CEXP = 0.3535533905932738f * 1.44269504f;

    int gwarp = (blockIdx.x * blockDim.x + threadIdx.x) >> 5;
    int lane = threadIdx.x & 31;
    int half = lane >> 4;
    int sub = lane & 15;
    int e = gwarp * 2 + half;
    bool valid = (e < E);
    int eidx = valid ? e : 0;

    int s = __ldg(&esrc[eidx]);
    int d = __ldg(&edst[eidx]);
    int dd = abs(d - s);
    float ew = (dd > 8) ? 1.0f : ((dd == 8) ? 0.0f : -1.0f);

    const unsigned char* fa = g_featA + (size_t)d * (6 * O);
    const unsigned char* fb = g_featB + (size_t)s * (6 * O);

    uint4 ua = __ldg((const uint4*)(fa + sub * 16));
    uint4 ub = __ldg((const uint4*)(fb + sub * 16));
    uint2 uva = __ldg((const uint2*)(fa + 4 * O + sub * 8));
    uint2 uvb = __ldg((const uint2*)(fb + 4 * O + sub * 8));

    __nv_bfloat162 qa2[2] = {*(__nv_bfloat162*)&ua.x, *(__nv_bfloat162*)&ua.y};
    __nv_bfloat162 ka2[2] = {*(__nv_bfloat162*)&ua.z, *(__nv_bfloat162*)&ua.w};
    __nv_bfloat162 qb2[2] = {*(__nv_bfloat162*)&ub.x, *(__nv_bfloat162*)&ub.y};
    __nv_bfloat162 kb2[2] = {*(__nv_bfloat162*)&ub.z, *(__nv_bfloat162*)&ub.w};
    __half2 va2[2] = {*(__half2*)&uva.x, *(__half2*)&uva.y};
    __half2 vb2[2] = {*(__half2*)&uvb.x, *(__half2*)&uvb.y};

    float p[4], vsum[4], sum = 0.0f;
#pragma unroll
    for (int h = 0; h < 2; h++) {
        __nv_bfloat162 t = __hmul2(__hadd2(qa2[h], qb2[h]), __hadd2(ka2[h], kb2[h]));
        float2 f = __bfloat1622float2(t);
        p[2 * h] = ex2f(f.x * CEXP);
        p[2 * h + 1] = ex2f(f.y * CEXP);
        sum += p[2 * h] + p[2 * h + 1];
        float2 fa2 = __half22float2(va2[h]);
        float2 fb2 = __half22float2(vb2[h]);
        vsum[2 * h] = fa2.x + fb2.x;
        vsum[2 * h + 1] = fa2.y + fb2.y;
    }
    sum += __shfl_xor_sync(0xFFFFFFFFu, sum, 1);
    float w = ew * rcpf(sum);

    float ctx[4];
#pragma unroll
    for (int i = 0; i < 4; i++) ctx[i] = p[i] * w * vsum[i];

    if (valid) {
        float* ap = g_acc + (size_t)d * O + sub * 4;
        asm volatile("red.global.add.v4.f32 [%0], {%1, %2, %3, %4};" ::"l"(ap),
                     "f"(ctx[0]), "f"(ctx[1]), "f"(ctx[2]), "f"(ctx[3])
                     : "memory");
        if (sub == 0) atomicAdd(&g_cnt[d], 1.0f);
    }
}

// ---------------- finalize (float4 per thread): mean/residual/relu -----------
// mode 0: g_x0 = rna(relu(acc/cnt)); mode 1: g_h1 = rna(relu(acc/cnt));
// mode 2: out = relu(acc/cnt + g_x0). Re-arms acc for modes 0/1.
__global__ void finalize_kernel(float* __restrict__ outp, int O, int mode) {
    int idx = blockIdx.x * blockDim.x + threadIdx.x;  // float4 index
    int total4 = NN * O / 4;
    if (idx >= total4) return;
    int u = idx / (O / 4);
    float inv = 1.0f / fmaxf(g_cnt[u], 1.0f);
    float4 a = ((float4*)g_acc)[idx];
    if (mode != 2) ((float4*)g_acc)[idx] = make_float4(0.f, 0.f, 0.f, 0.f);
    float vv[4] = {a.x * inv, a.y * inv, a.z * inv, a.w * inv};
    if (mode == 2) {
        float4 r = ((const float4*)g_x0)[idx];
        float4 o;
        o.x = fmaxf(vv[0] + r.x, 0.0f);
        o.y = fmaxf(vv[1] + r.y, 0.0f);
        o.z = fmaxf(vv[2] + r.z, 0.0f);
        o.w = fmaxf(vv[3] + r.w, 0.0f);
        ((float4*)outp)[idx] = o;
    } else {
        float4 o;
        o.x = rna_tf32(fmaxf(vv[0], 0.0f));
        o.y = rna_tf32(fmaxf(vv[1], 0.0f));
        o.z = rna_tf32(fmaxf(vv[2], 0.0f));
        o.w = rna_tf32(fmaxf(vv[3], 0.0f));
        if (mode == 0)
            ((float4*)g_x0)[idx] = o;
        else
            ((float4*)g_h1)[idx] = o;
    }
}

// ---------------- launch -----------------------------------------------------
extern "C" void kernel_launch(void* const* d_in, const int* in_sizes, int n_in,
                              void* d_out, int out_size) {
    const float* x = (const float*)d_in[0];
    const int* e0 = (const int*)d_in[1];
    const int* e1 = (const int*)d_in[2];
    const int* e2 = (const int*)d_in[3];
    const float* wq0 = (const float*)d_in[5];
    const float* bq0 = (const float*)d_in[6];
    const float* wk0 = (const float*)d_in[7];
    const float* bk0 = (const float*)d_in[8];
    const float* wv0 = (const float*)d_in[9];
    const float* bv0 = (const float*)d_in[10];
    const float* wq1 = (const float*)d_in[11];
    const float* bq1 = (const float*)d_in[12];
    const float* wk1 = (const float*)d_in[13];
    const float* bk1 = (const float*)d_in[14];
    const float* wv1 = (const float*)d_in[15];
    const float* bv1 = (const float*)d_in[16];
    const float* wq2 = (const float*)d_in[17];
    const float* bq2 = (const float*)d_in[18];
    const float* wk2 = (const float*)d_in[19];
    const float* bk2 = (const float*)d_in[20];
    const float* wv2 = (const float*)d_in[21];
    const float* bv2 = (const float*)d_in[22];

    int E0 = in_sizes[1] / 2;
    int E1 = in_sizes[2] / 2;
    int E2 = in_sizes[3] / 2;

    int fin4_128 = (NN * 128 / 4 + 255) / 256;
    int fin4_64 = (NN * 64 / 4 + 255) / 256;
    int nblk = (NN + 127) / 128;
    int bw0 = (128 * 768 + 255) / 256;
    int bw1 = max((128 * 384 + 255) / 256, (NN + 255) / 256);
    int bw2 = max((64 * 768 + 255) / 256, (NN + 255) / 256);

    zero_acc<<<fin4_128, 256>>>(NN * 128 / 4);  // one-time; finalize re-arms after

    // ---- Layer 0: C=128, O=128 ----
    build_wcat<<<bw0, 256>>>(wq0, wk0, wv0, bq0, bk0, bv0, 128, 128);
    mma_gemm<128, 128, true><<<dim3(6, nblk), 256>>>(x, 0, NN);
    edge_kernel128<<<(E0 + 7) / 8, 256>>>(e0, e0 + E0, E0);
    finalize_kernel<<<fin4_128, 256>>>(nullptr, 128, 0);

    // ---- Layer 1: C=128, O=64 ----
    build_wcat<<<bw1, 256>>>(wq1, wk1, wv1, bq1, bk1, bv1, 128, 64);
    mma_gemm<128, 64, false><<<dim3(3, nblk), 256>>>(nullptr, 1, NN);
    edge_kernel64<<<((E1 + 1) / 2 + 7) / 8, 256>>>(e1, e1 + E1, E1);
    finalize_kernel<<<fin4_64, 256>>>(nullptr, 64, 1);

    // ---- Layer 2: C=64, O=128 ----
    build_wcat<<<bw2, 256>>>(wq2, wk2, wv2, bq2, bk2, bv2, 64, 128);
    mma_gemm<64, 128, false><<<dim3(6, nblk), 256>>>(nullptr, 2, NN);
    edge_kernel128<<<(E2 + 7) / 8, 256>>>(e2, e2 + E2, E2);
    finalize_kernel<<<fin4_128, 256>>>((float*)d_out, 128, 2);
}

// round 16
// speedup vs baseline: 1.1018x; 1.1018x over previous
#include <cuda_runtime.h>
#include <cuda_bf16.h>
#include <cuda_fp16.h>
#include <math.h>
#include <stdint.h>

#define NN 50000

// ---------------- scratch (device globals; no allocations allowed) ----------
// Split per-node features. A = dst-side, B = src-side. Stride 6*O bytes:
//   [0   ,2O ) q  bf16[O]
//   [2O  ,4O ) k  bf16[O]
//   [4O  ,6O ) v  fp16[O]
__device__ __align__(16) unsigned char g_featA[NN * 768];
__device__ __align__(16) unsigned char g_featB[NN * 768];
__device__ float g_x0[NN * 128];        // relu(layer0 out) f32 (residual)
__device__ __half g_xh[NN * 128];       // fp16 copy of input x (L0 GEMM input)
__device__ __half g_x0h[NN * 128];      // fp16 relu(layer0 out) (L1 GEMM input)
__device__ __half g_h1h[NN * 64];       // fp16 relu(layer1 out) (L2 GEMM input)
__device__ float g_acc[NN * 128];       // edge-aggregation accumulator (f32)
__device__ float g_cnt[NN];             // edge count per dst
__device__ __half g_wcatTh[768 * 128];  // transposed transformed weights [M][K], fp16
__device__ float g_bcat[768];           // concatenated bias (bias only on A columns)

__device__ __forceinline__ float ex2f(float v) {
    float o;
    asm("ex2.approx.f32 %0, %1;" : "=f"(o) : "f"(v));
    return o;
}
__device__ __forceinline__ float rcpf(float v) {
    float o;
    asm("rcp.approx.f32 %0, %1;" : "=f"(o) : "f"(v));
    return o;
}

// ---------------- build W_catTh[col][c] = fp16([Wtop-Wbot | Wbot]); zero cnt -
__global__ void build_wcat(const float* __restrict__ wq, const float* __restrict__ wk,
                           const float* __restrict__ wv, const float* __restrict__ bq,
                           const float* __restrict__ bk, const float* __restrict__ bv,
                           int C, int O) {
    int M = 6 * O;
    int idx = blockIdx.x * blockDim.x + threadIdx.x;
    if (idx < C * M) {
        int c = idx / M, col = idx % M;
        int grp = col / O, j = col % O;
        const float* w = (grp < 2) ? wq : (grp < 4 ? wk : wv);
        float top = w[c * O + j];
        float bot = w[(C + c) * O + j];
        float val = (grp & 1) ? bot : (top - bot);
        g_wcatTh[(size_t)col * C + c] = __float2half_rn(val);
    }
    if (idx < M) {
        int grp = idx / O, j = idx % O;
        const float* b = (grp < 2) ? bq : (grp < 4 ? bk : bv);
        g_bcat[idx] = (grp & 1) ? 0.0f : b[j];
    }
    if (idx < NN) g_cnt[idx] = 0.0f;  // prepare edge-count for this layer
}

// ---------------- one-time: zero acc, convert x -> fp16 ----------------------
__global__ void zero_acc(int n4) {
    int idx = blockIdx.x * blockDim.x + threadIdx.x;
    if (idx < n4) ((float4*)g_acc)[idx] = make_float4(0.f, 0.f, 0.f, 0.f);
}
__global__ void convert_x(const float* __restrict__ x, int n2) {
    int idx = blockIdx.x * blockDim.x + threadIdx.x;  // float2 index
    if (idx < n2) {
        float2 f = ((const float2*)x)[idx];
        ((__half2*)g_xh)[idx] = __floats2half2_rn(f.x, f.y);
    }
}

// ---------------- fp16 tensor-core GEMM (m16n8k16) ---------------------------
// feat = A(NxK) @ g_wcatTh^T + bias, A fp16 (g_xh/g_x0h/g_h1h), B fp16.
// 128x128 CTA tile, BK=32, 8 warps of 64x32, double-buffered cp.async.
// srcsel: 0 -> g_xh, 1 -> g_x0h, 2 -> g_h1h.
template <int K, int O>
__global__ __launch_bounds__(256, 2) void mma_gemm(int srcsel, int N) {
    const __half* A = (srcsel == 0) ? g_xh : ((srcsel == 1) ? g_x0h : g_h1h);
    constexpr int PADH = 40;  // halfs per row: 32 data + 8 pad = 80 B (cf-free)
    __shared__ __half As[2][128 * PADH];
    __shared__ __half Bs[2][128 * PADH];

    const int tid = threadIdx.x;
    const int lane = tid & 31;
    const int wid = tid >> 5;
    const int wm = (wid & 1) * 64;
    const int wn = (wid >> 1) * 32;
    const int bm = blockIdx.y * 128;
    const int bn = blockIdx.x * 128;

    float acc[4][4][4];
#pragma unroll
    for (int a = 0; a < 4; a++)
#pragma unroll
        for (int b = 0; b < 4; b++)
#pragma unroll
            for (int c = 0; c < 4; c++) acc[a][b][c] = 0.0f;

    const int r_ld = tid >> 1;          // 0..127
    const int ch0 = (tid & 1) * 2;      // 2 chunks of 8 halfs each
    const int garow = bm + r_ld;
    const __half* aptr = A + (size_t)(garow < N ? garow : 0) * K;
    const int asz = (garow < N) ? 16 : 0;
    const __half* bptr = g_wcatTh + (size_t)(bn + r_ld) * K;

#define SMADDR(p) ((uint32_t)__cvta_generic_to_shared(p))

#define LOAD_STAGE(buf, k0)                                                          \
    {                                                                                \
        _Pragma("unroll") for (int i = 0; i < 2; i++) {                              \
            int ch = ch0 + i;                                                        \
            asm volatile("cp.async.cg.shared.global [%0], [%1], 16, %2;" ::"r"(      \
                             SMADDR(&As[buf][r_ld * PADH + ch * 8])),                \
                         "l"(aptr + (k0) + ch * 8), "r"(asz));                       \
            asm volatile("cp.async.cg.shared.global [%0], [%1], 16;" ::"r"(          \
                             SMADDR(&Bs[buf][r_ld * PADH + ch * 8])),                \
                         "l"(bptr + (k0) + ch * 8));                                 \
        }                                                                            \
        asm volatile("cp.async.commit_group;");                                      \
    }

    LOAD_STAGE(0, 0);
    constexpr int NIT = K / 32;
#pragma unroll
    for (int it = 0; it < NIT; it++) {
        const int buf = it & 1;
        if (it + 1 < NIT) {
            LOAD_STAGE(buf ^ 1, (it + 1) * 32);
            asm volatile("cp.async.wait_group 1;");
        } else {
            asm volatile("cp.async.wait_group 0;");
        }
        __syncthreads();

#pragma unroll
        for (int ks = 0; ks < 32; ks += 16) {
            uint32_t af[4][4];
#pragma unroll
            for (int mt = 0; mt < 4; mt++) {
                const __half* p = &As[buf][(wm + mt * 16 + (lane & 15)) * PADH + ks +
                                           (lane >> 4) * 8];
                asm volatile(
                    "ldmatrix.sync.aligned.m8n8.x4.shared.b16 {%0,%1,%2,%3}, [%4];"
                    : "=r"(af[mt][0]), "=r"(af[mt][1]), "=r"(af[mt][2]), "=r"(af[mt][3])
                    : "r"(SMADDR(p)));
            }
            uint32_t bf[2][4];
#pragma unroll
            for (int bi = 0; bi < 2; bi++) {
                const __half* p = &Bs[buf][(wn + bi * 16 + (lane & 15)) * PADH + ks +
                                           (lane >> 4) * 8];
                asm volatile(
                    "ldmatrix.sync.aligned.m8n8.x4.shared.b16 {%0,%1,%2,%3}, [%4];"
                    : "=r"(bf[bi][0]), "=r"(bf[bi][1]), "=r"(bf[bi][2]), "=r"(bf[bi][3])
                    : "r"(SMADDR(p)));
            }
#pragma unroll
            for (int mt = 0; mt < 4; mt++)
#pragma unroll
                for (int nt = 0; nt < 4; nt++) {
                    uint32_t b0 = bf[nt >> 1][(nt & 1)];
                    uint32_t b1 = bf[nt >> 1][(nt & 1) + 2];
                    asm volatile(
                        "mma.sync.aligned.m16n8k16.row.col.f32.f16.f16.f32 "
                        "{%0,%1,%2,%3}, {%4,%5,%6,%7}, {%8,%9}, {%0,%1,%2,%3};"
                        : "+f"(acc[mt][nt][0]), "+f"(acc[mt][nt][1]),
                          "+f"(acc[mt][nt][2]), "+f"(acc[mt][nt][3])
                        : "r"(af[mt][0]), "r"(af[mt][1]), "r"(af[mt][2]),
                          "r"(af[mt][3]), "r"(b0), "r"(b1));
                }
        }
        __syncthreads();
    }

    // Epilogue: add bias, write split A/B layout (q/k bf16, v fp16; stride 6*O).
#pragma unroll
    for (int mt = 0; mt < 4; mt++) {
        int r = bm + wm + mt * 16 + (lane >> 2);
#pragma unroll
        for (int half = 0; half < 2; half++) {
            int rr = r + half * 8;
            if (rr < N) {
                unsigned char* baseA = g_featA + (size_t)rr * (6 * O);
                unsigned char* baseB = g_featB + (size_t)rr * (6 * O);
#pragma unroll
                for (int nt = 0; nt < 4; nt++) {
                    int c = bn + wn + nt * 8 + (lane & 3) * 2;
                    int grp = c / O;
                    int j = c - grp * O;
                    float ox = acc[mt][nt][half * 2 + 0] + g_bcat[c];
                    float oy = acc[mt][nt][half * 2 + 1] + g_bcat[c + 1];
                    unsigned char* base = (grp & 1) ? baseB : baseA;
                    int reg = grp >> 1;  // 0=q, 1=k, 2=v
                    if (reg < 2) {
                        __nv_bfloat162 h2 = __floats2bfloat162_rn(ox, oy);
                        *(__nv_bfloat162*)(base + reg * (2 * O) + j * 2) = h2;
                    } else {
                        __half2 h2 = __floats2half2_rn(ox, oy);
                        *(__half2*)(base + 4 * O + j * 2) = h2;
                    }
                }
            }
        }
    }
#undef LOAD_STAGE
#undef SMADDR
}

// ---------------- edge kernel, O=128: ONE edge per warp ----------------------
// CPT=4 channels/lane. q/k bf16, v fp16. No max-subtraction; rcp.approx.
__global__ __launch_bounds__(256) void edge_kernel128(const int* __restrict__ esrc,
                                                      const int* __restrict__ edst,
                                                      int E) {
    constexpr int O = 128;
    const float CEXP = 0.25f * 1.44269504f;

    int gwarp = (blockIdx.x * blockDim.x + threadIdx.x) >> 5;
    int lane = threadIdx.x & 31;
    if (gwarp >= E) return;

    int s = esrc[gwarp];
    int d = edst[gwarp];
    int dd = abs(d - s);
    float ew = (dd > 8) ? 1.0f : ((dd == 8) ? 0.0f : -1.0f);

    const unsigned char* fa = g_featA + (size_t)d * (6 * O);
    const unsigned char* fb = g_featB + (size_t)s * (6 * O);
    int c = lane * 4;

    __nv_bfloat162 qa2[2], ka2[2], qb2[2], kb2[2];
    __half2 va2[2], vb2[2];
    uint2 u;
    u = __ldg((const uint2*)(fa + c * 2));
    qa2[0] = *(__nv_bfloat162*)&u.x; qa2[1] = *(__nv_bfloat162*)&u.y;
    u = __ldg((const uint2*)(fa + 2 * O + c * 2));
    ka2[0] = *(__nv_bfloat162*)&u.x; ka2[1] = *(__nv_bfloat162*)&u.y;
    u = __ldg((const uint2*)(fa + 4 * O + c * 2));
    va2[0] = *(__half2*)&u.x; va2[1] = *(__half2*)&u.y;
    u = __ldg((const uint2*)(fb + c * 2));
    qb2[0] = *(__nv_bfloat162*)&u.x; qb2[1] = *(__nv_bfloat162*)&u.y;
    u = __ldg((const uint2*)(fb + 2 * O + c * 2));
    kb2[0] = *(__nv_bfloat162*)&u.x; kb2[1] = *(__nv_bfloat162*)&u.y;
    u = __ldg((const uint2*)(fb + 4 * O + c * 2));
    vb2[0] = *(__half2*)&u.x; vb2[1] = *(__half2*)&u.y;

    float p[4], vsum[4], sum = 0.0f;
#pragma unroll
    for (int h = 0; h < 2; h++) {
        __nv_bfloat162 t = __hmul2(__hadd2(qa2[h], qb2[h]), __hadd2(ka2[h], kb2[h]));
        float2 f = __bfloat1622float2(t);
        p[2 * h] = ex2f(f.x * CEXP);
        p[2 * h + 1] = ex2f(f.y * CEXP);
        sum += p[2 * h] + p[2 * h + 1];
        float2 fa2 = __half22float2(va2[h]);
        float2 fb2 = __half22float2(vb2[h]);
        vsum[2 * h] = fa2.x + fb2.x;
        vsum[2 * h + 1] = fa2.y + fb2.y;
    }
    sum += __shfl_xor_sync(0xFFFFFFFFu, sum, 1);
    sum += __shfl_xor_sync(0xFFFFFFFFu, sum, 2);
    float w = ew * rcpf(sum);

    float ctx[4];
#pragma unroll
    for (int i = 0; i < 4; i++) ctx[i] = p[i] * w * vsum[i];

    float* ap = g_acc + (size_t)d * O + c;
    asm volatile("red.global.add.v4.f32 [%0], {%1, %2, %3, %4};" ::"l"(ap),
                 "f"(ctx[0]), "f"(ctx[1]), "f"(ctx[2]), "f"(ctx[3])
                 : "memory");
    if (lane == 0) atomicAdd(&g_cnt[d], 1.0f);
}

// ---------------- edge kernel, O=64: TWO edges per warp ----------------------
__global__ __launch_bounds__(256) void edge_kernel64(const int* __restrict__ esrc,
                                                     const int* __restrict__ edst,
                                                     int E) {
    constexpr int O = 64;
    const float CEXP = 0.3535533905932738f * 1.44269504f;

    int gwarp = (blockIdx.x * blockDim.x + threadIdx.x) >> 5;
    int lane = threadIdx.x & 31;
    int half = lane >> 4;
    int sub = lane & 15;
    int e = gwarp * 2 + half;
    bool valid = (e < E);
    int eidx = valid ? e : 0;

    int s = __ldg(&esrc[eidx]);
    int d = __ldg(&edst[eidx]);
    int dd = abs(d - s);
    float ew = (dd > 8) ? 1.0f : ((dd == 8) ? 0.0f : -1.0f);

    const unsigned char* fa = g_featA + (size_t)d * (6 * O);
    const unsigned char* fb = g_featB + (size_t)s * (6 * O);
    int c = sub * 4;

    __nv_bfloat162 qa2[2], ka2[2], qb2[2], kb2[2];
    __half2 va2[2], vb2[2];
    uint2 u;
    u = __ldg((const uint2*)(fa + c * 2));
    qa2[0] = *(__nv_bfloat162*)&u.x; qa2[1] = *(__nv_bfloat162*)&u.y;
    u = __ldg((const uint2*)(fa + 2 * O + c * 2));
    ka2[0] = *(__nv_bfloat162*)&u.x; ka2[1] = *(__nv_bfloat162*)&u.y;
    u = __ldg((const uint2*)(fa + 4 * O + c * 2));
    va2[0] = *(__half2*)&u.x; va2[1] = *(__half2*)&u.y;
    u = __ldg((const uint2*)(fb + c * 2));
    qb2[0] = *(__nv_bfloat162*)&u.x; qb2[1] = *(__nv_bfloat162*)&u.y;
    u = __ldg((const uint2*)(fb + 2 * O + c * 2));
    kb2[0] = *(__nv_bfloat162*)&u.x; kb2[1] = *(__nv_bfloat162*)&u.y;
    u = __ldg((const uint2*)(fb + 4 * O + c * 2));
    vb2[0] = *(__half2*)&u.x; vb2[1] = *(__half2*)&u.y;

    float p[4], vsum[4], sum = 0.0f;
#pragma unroll
    for (int h = 0; h < 2; h++) {
        __nv_bfloat162 t = __hmul2(__hadd2(qa2[h], qb2[h]), __hadd2(ka2[h], kb2[h]));
        float2 f = __bfloat1622float2(t);
        p[2 * h] = ex2f(f.x * CEXP);
        p[2 * h + 1] = ex2f(f.y * CEXP);
        sum += p[2 * h] + p[2 * h + 1];
        float2 fa2 = __half22float2(va2[h]);
        float2 fb2 = __half22float2(vb2[h]);
        vsum[2 * h] = fa2.x + fb2.x;
        vsum[2 * h + 1] = fa2.y + fb2.y;
    }
    sum += __shfl_xor_sync(0xFFFFFFFFu, sum, 1);
    float w = ew * rcpf(sum);

    float ctx[4];
#pragma unroll
    for (int i = 0; i < 4; i++) ctx[i] = p[i] * w * vsum[i];

    if (valid) {
        float* ap = g_acc + (size_t)d * O + c;
        asm volatile("red.global.add.v4.f32 [%0], {%1, %2, %3, %4};" ::"l"(ap),
                     "f"(ctx[0]), "f"(ctx[1]), "f"(ctx[2]), "f"(ctx[3])
                     : "memory");
        if (sub == 0) atomicAdd(&g_cnt[d], 1.0f);
    }
}

// ---------------- finalize (float4 per thread): mean/residual/relu -----------
// mode 0: g_x0 = relu(acc/cnt) f32 AND g_x0h = fp16 copy;
// mode 1: g_h1h = fp16(relu(acc/cnt));
// mode 2: out = relu(acc/cnt + g_x0). Re-arms acc for modes 0/1.
__global__ void finalize_kernel(float* __restrict__ outp, int O, int mode) {
    int idx = blockIdx.x * blockDim.x + threadIdx.x;  // float4 index
    int total4 = NN * O / 4;
    if (idx >= total4) return;
    int u = idx / (O / 4);
    float inv = 1.0f / fmaxf(g_cnt[u], 1.0f);
    float4 a = ((float4*)g_acc)[idx];
    if (mode != 2) ((float4*)g_acc)[idx] = make_float4(0.f, 0.f, 0.f, 0.f);
    float vv[4] = {a.x * inv, a.y * inv, a.z * inv, a.w * inv};
    if (mode == 2) {
        float4 r = ((const float4*)g_x0)[idx];
        float4 o;
        o.x = fmaxf(vv[0] + r.x, 0.0f);
        o.y = fmaxf(vv[1] + r.y, 0.0f);
        o.z = fmaxf(vv[2] + r.z, 0.0f);
        o.w = fmaxf(vv[3] + r.w, 0.0f);
        ((float4*)outp)[idx] = o;
    } else {
        float4 o;
        o.x = fmaxf(vv[0], 0.0f);
        o.y = fmaxf(vv[1], 0.0f);
        o.z = fmaxf(vv[2], 0.0f);
        o.w = fmaxf(vv[3], 0.0f);
        __half2 h0 = __floats2half2_rn(o.x, o.y);
        __half2 h1 = __floats2half2_rn(o.z, o.w);
        if (mode == 0) {
            ((float4*)g_x0)[idx] = o;
            ((__half2*)g_x0h)[idx * 2] = h0;
            ((__half2*)g_x0h)[idx * 2 + 1] = h1;
        } else {
            ((__half2*)g_h1h)[idx * 2] = h0;
            ((__half2*)g_h1h)[idx * 2 + 1] = h1;
        }
    }
}

// ---------------- launch -----------------------------------------------------
extern "C" void kernel_launch(void* const* d_in, const int* in_sizes, int n_in,
                              void* d_out, int out_size) {
    const float* x = (const float*)d_in[0];
    const int* e0 = (const int*)d_in[1];
    const int* e1 = (const int*)d_in[2];
    const int* e2 = (const int*)d_in[3];
    const float* wq0 = (const float*)d_in[5];
    const float* bq0 = (const float*)d_in[6];
    const float* wk0 = (const float*)d_in[7];
    const float* bk0 = (const float*)d_in[8];
    const float* wv0 = (const float*)d_in[9];
    const float* bv0 = (const float*)d_in[10];
    const float* wq1 = (const float*)d_in[11];
    const float* bq1 = (const float*)d_in[12];
    const float* wk1 = (const float*)d_in[13];
    const float* bk1 = (const float*)d_in[14];
    const float* wv1 = (const float*)d_in[15];
    const float* bv1 = (const float*)d_in[16];
    const float* wq2 = (const float*)d_in[17];
    const float* bq2 = (const float*)d_in[18];
    const float* wk2 = (const float*)d_in[19];
    const float* bk2 = (const float*)d_in[20];
    const float* wv2 = (const float*)d_in[21];
    const float* bv2 = (const float*)d_in[22];

    int E0 = in_sizes[1] / 2;
    int E1 = in_sizes[2] / 2;
    int E2 = in_sizes[3] / 2;

    int fin4_128 = (NN * 128 / 4 + 255) / 256;
    int fin4_64 = (NN * 64 / 4 + 255) / 256;
    int nblk = (NN + 127) / 128;
    int bw0 = (128 * 768 + 255) / 256;
    int bw1 = max((128 * 384 + 255) / 256, (NN + 255) / 256);
    int bw2 = max((64 * 768 + 255) / 256, (NN + 255) / 256);

    zero_acc<<<fin4_128, 256>>>(NN * 128 / 4);  // one-time; finalize re-arms after
    convert_x<<<(NN * 128 / 2 + 255) / 256, 256>>>(x, NN * 128 / 2);

    // ---- Layer 0: C=128, O=128 ----
    build_wcat<<<bw0, 256>>>(wq0, wk0, wv0, bq0, bk0, bv0, 128, 128);
    mma_gemm<128, 128><<<dim3(6, nblk), 256>>>(0, NN);
    edge_kernel128<<<(E0 + 7) / 8, 256>>>(e0, e0 + E0, E0);
    finalize_kernel<<<fin4_128, 256>>>(nullptr, 128, 0);

    // ---- Layer 1: C=128, O=64 ----
    build_wcat<<<bw1, 256>>>(wq1, wk1, wv1, bq1, bk1, bv1, 128, 64);
    mma_gemm<128, 64><<<dim3(3, nblk), 256>>>(1, NN);
    edge_kernel64<<<((E1 + 1) / 2 + 7) / 8, 256>>>(e1, e1 + E1, E1);
    finalize_kernel<<<fin4_64, 256>>>(nullptr, 64, 1);

    // ---- Layer 2: C=64, O=128 ----
    build_wcat<<<bw2, 256>>>(wq2, wk2, wv2, bq2, bk2, bv2, 64, 128);
    mma_gemm<64, 128><<<dim3(6, nblk), 256>>>(2, NN);
    edge_kernel128<<<(E2 + 7) / 8, 256>>>(e2, e2 + E2, E2);
    finalize_kernel<<<fin4_128, 256>>>((float*)d_out, 128, 2);
}